// round 10
// baseline (speedup 1.0000x reference)
#include <cuda_runtime.h>
#include <cuda_bf16.h>
#include <cstdint>

// out[b,g,k] = sum_d (h[b,g,d]/||h||) * (w[g,d,k]/||w_col||)
// B=512, G=100, D=768, K=100.
// bf16 two-term split, 3-product HMMA, ldmatrix, double-buffered smem.
// R6 shape (128x128 CTA, 8 warps, warp 64x32, BKC=32, 2 CTAs/SM),
// h row-norms fused into the GEMM prologue (norm_h kernel eliminated).

#define B_ 512
#define G_ 100
#define D_ 768
#define K_ 100
#define KP 128
#define BKC 32              // k-chunk
#define NCHUNK (D_ / BKC)   // 24
#define LDB 80              // smem row stride bytes (32 bf16 + pad)

#define AH_OFF 0
#define AL_OFF 10240
#define BH_OFF 20480
#define BL_OFF 30720
#define STAGE_BYTES 40960

// ---------------- device scratch ----------------
__device__ float g_inv_w[G_ * K_];
__device__ __nv_bfloat16 g_wt_hi[(size_t)G_ * KP * D_];
__device__ __nv_bfloat16 g_wt_lo[(size_t)G_ * KP * D_];

// ---------------- helpers ----------------
__device__ __forceinline__ uint32_t smem_u32(const void* p) {
    uint32_t a;
    asm("{ .reg .u64 t; cvta.to.shared.u64 t, %1; cvt.u32.u64 %0, t; }"
        : "=r"(a) : "l"(p));
    return a;
}

#define MMA_BF16(d, a, b0, b1)                                              \
    asm volatile(                                                           \
        "mma.sync.aligned.m16n8k16.row.col.f32.bf16.bf16.f32 "              \
        "{%0,%1,%2,%3}, {%4,%5,%6,%7}, {%8,%9}, {%0,%1,%2,%3};"             \
        : "+f"(d[0]), "+f"(d[1]), "+f"(d[2]), "+f"(d[3])                    \
        : "r"(a[0]), "r"(a[1]), "r"(a[2]), "r"(a[3]), "r"(b0), "r"(b1))

#define LDSM4(r, addr)                                                      \
    asm volatile("ldmatrix.sync.aligned.m8n8.x4.shared.b16 "                \
                 "{%0,%1,%2,%3}, [%4];"                                     \
                 : "=r"((r)[0]), "=r"((r)[1]), "=r"((r)[2]), "=r"((r)[3])   \
                 : "r"(addr))

#define CP16(dst, src)                                                      \
    asm volatile("cp.async.cg.shared.global [%0], [%1], 16;"                \
                 :: "r"(dst), "l"(src) : "memory")
#define CP_COMMIT() asm volatile("cp.async.commit_group;" ::: "memory")
#define CP_WAIT0()  asm volatile("cp.async.wait_group 0;" ::: "memory")

// ---------------------------------------------------------------------------
__global__ void norm_w_kernel(const float* __restrict__ w) {
    __shared__ float partial[4][128];
    int g = blockIdx.x;
    int k = threadIdx.x & 127;
    int c = threadIdx.x >> 7;
    float s = 0.f;
    if (k < K_) {
        const float* base = w + (size_t)g * D_ * K_ + (size_t)c * 192 * K_ + k;
#pragma unroll 8
        for (int d = 0; d < 192; d++) {
            float v = base[(size_t)d * K_];
            s += v * v;
        }
    }
    partial[c][k] = s;
    __syncthreads();
    if (c == 0 && k < K_) {
        float t = partial[0][k] + partial[1][k] + partial[2][k] + partial[3][k];
        g_inv_w[g * K_ + k] = 1.0f / fmaxf(sqrtf(t), 1e-12f);
    }
}

__global__ void split_w_kernel(const float* __restrict__ w) {
    __shared__ float ws[64][104];
    const int dc = blockIdx.x;
    const int g  = blockIdx.y;
    const int tid = threadIdx.x;
    const float* src = w + (size_t)g * D_ * K_ + (size_t)dc * 64 * K_;
#pragma unroll
    for (int i = 0; i < 25; i++) {
        int idx = tid + 256 * i;
        ws[idx / K_][idx % K_] = src[idx];
    }
    __syncthreads();
    const int k  = tid >> 1;
    const int d0 = (tid & 1) * 32;
    float invw = (k < K_) ? g_inv_w[g * K_ + k] : 0.f;
    __nv_bfloat16 hb[32], lb[32];
#pragma unroll
    for (int j = 0; j < 32; j++) {
        float x = (k < K_) ? ws[d0 + j][k] * invw : 0.f;
        __nv_bfloat16 hi = __float2bfloat16(x);
        hb[j] = hi;
        lb[j] = __float2bfloat16(x - __bfloat162float(hi));
    }
    size_t base = ((size_t)g * KP + k) * D_ + (size_t)dc * 64 + d0;
    uint4* dh = reinterpret_cast<uint4*>(g_wt_hi + base);
    uint4* dl = reinterpret_cast<uint4*>(g_wt_lo + base);
#pragma unroll
    for (int q = 0; q < 4; q++) {
        dh[q] = *reinterpret_cast<const uint4*>(hb + q * 8);
        dl[q] = *reinterpret_cast<const uint4*>(lb + q * 8);
    }
}

// ---------------------------------------------------------------------------
// HMMA GEMM. CTA = (g, 128 rows), 8 warps: mw = warp&1 (64 rows),
// nw = warp>>1 (32 cols). Warp tile 64x32, 3 bf16 products, fp32 acc.
// h row norms computed in the prologue (each thread: half-row sumsq + shfl).
// ---------------------------------------------------------------------------
__global__ __launch_bounds__(256, 2)
void gemm_hmma_kernel(const float* __restrict__ h, float* __restrict__ out) {
    extern __shared__ char smem[];
    const uint32_t sb = smem_u32(smem);
    const int tid  = threadIdx.x;
    const int lane = tid & 31;
    const int warp = tid >> 5;
    const int mw = warp & 1;
    const int nw = warp >> 1;
    const int g  = blockIdx.y;
    const int m0 = blockIdx.x * 128;

    // ---- global load mapping: 2 threads per row, 16 elems each ----
    const int arow = tid >> 1;
    const int half = tid & 1;
    const float* gArow = h + ((size_t)(m0 + arow) * G_ + g) * D_;
    const float* gA = gArow + half * 16;
    const char* gBh = reinterpret_cast<const char*>(
        g_wt_hi + ((size_t)g * KP + arow) * D_) + half * 32;
    const char* gBl = reinterpret_cast<const char*>(
        g_wt_lo + ((size_t)g * KP + arow) * D_) + half * 32;

    const uint32_t srow = arow * LDB + half * 32;

    // ldmatrix base addresses (stage-relative)
    const uint32_t a_lm = (mw * 64 + (lane & 15)) * LDB + (lane >> 4) * 16;
    const uint32_t b_lm = (nw * 32 + (lane & 7) + ((lane >> 4) & 1) * 8) * LDB
                        + ((lane >> 3) & 1) * 16;

    // ---- kick off B chunk 0 before the norm pass (overlap) ----
    auto cp_B = [&](int c, uint32_t stage) {
        CP16(stage + BH_OFF + srow,      gBh + (size_t)c * 64);
        CP16(stage + BH_OFF + srow + 16, gBh + (size_t)c * 64 + 16);
        CP16(stage + BL_OFF + srow,      gBl + (size_t)c * 64);
        CP16(stage + BL_OFF + srow + 16, gBl + (size_t)c * 64 + 16);
    };
    cp_B(0, sb);
    CP_COMMIT();

    // ---- fused h row norm: each thread sums its half row (384 elems) ----
    float invh;
    {
        const float4* p = reinterpret_cast<const float4*>(gArow) + half * 96;
        float s = 0.f;
#pragma unroll 8
        for (int i = 0; i < 96; i++) {
            float4 v = p[i];
            s += v.x * v.x + v.y * v.y + v.z * v.z + v.w * v.w;
        }
        s += __shfl_xor_sync(0xffffffffu, s, 1);   // combine the two halves
        invh = 1.0f / fmaxf(sqrtf(s), 1e-12f);
    }

    float acc[4][4][4];   // [mt][nf][reg]
#pragma unroll
    for (int mt = 0; mt < 4; mt++)
#pragma unroll
        for (int nf = 0; nf < 4; nf++)
#pragma unroll
            for (int r = 0; r < 4; r++) acc[mt][nf][r] = 0.f;

    // ---- A convert+store: 16 fp32 -> hi/lo bf16 (32B each) ----
    auto store_A = [&](const float4* av, uint32_t stage) {
        uint32_t uh[8], ul[8];
#pragma unroll
        for (int i = 0; i < 4; i++) {
            float x0 = av[i].x * invh, x1 = av[i].y * invh;
            float x2 = av[i].z * invh, x3 = av[i].w * invh;
            __nv_bfloat162 h0 = __float22bfloat162_rn(make_float2(x0, x1));
            __nv_bfloat162 h1 = __float22bfloat162_rn(make_float2(x2, x3));
            float2 f0 = __bfloat1622float2(h0), f1 = __bfloat1622float2(h1);
            __nv_bfloat162 l0 = __float22bfloat162_rn(make_float2(x0 - f0.x, x1 - f0.y));
            __nv_bfloat162 l1 = __float22bfloat162_rn(make_float2(x2 - f1.x, x3 - f1.y));
            uh[i * 2]     = *reinterpret_cast<uint32_t*>(&h0);
            uh[i * 2 + 1] = *reinterpret_cast<uint32_t*>(&h1);
            ul[i * 2]     = *reinterpret_cast<uint32_t*>(&l0);
            ul[i * 2 + 1] = *reinterpret_cast<uint32_t*>(&l1);
        }
        asm volatile("st.shared.v4.b32 [%0], {%1,%2,%3,%4};"
            :: "r"(stage + AH_OFF + srow), "r"(uh[0]), "r"(uh[1]), "r"(uh[2]), "r"(uh[3]) : "memory");
        asm volatile("st.shared.v4.b32 [%0], {%1,%2,%3,%4};"
            :: "r"(stage + AH_OFF + srow + 16), "r"(uh[4]), "r"(uh[5]), "r"(uh[6]), "r"(uh[7]) : "memory");
        asm volatile("st.shared.v4.b32 [%0], {%1,%2,%3,%4};"
            :: "r"(stage + AL_OFF + srow), "r"(ul[0]), "r"(ul[1]), "r"(ul[2]), "r"(ul[3]) : "memory");
        asm volatile("st.shared.v4.b32 [%0], {%1,%2,%3,%4};"
            :: "r"(stage + AL_OFF + srow + 16), "r"(ul[4]), "r"(ul[5]), "r"(ul[6]), "r"(ul[7]) : "memory");
    };

    // ---- prologue: fill stage 0 (A re-read hits L2, just streamed) ----
    {
        float4 av[4];
#pragma unroll
        for (int i = 0; i < 4; i++)
            av[i] = *reinterpret_cast<const float4*>(gA + i * 4);
        store_A(av, sb);
        CP_WAIT0();
    }
    __syncthreads();

    for (int c = 0; c < NCHUNK; c++) {
        const uint32_t stage  = sb + (uint32_t)(c & 1) * STAGE_BYTES;
        const uint32_t nstage = sb + (uint32_t)((c + 1) & 1) * STAGE_BYTES;

        float4 av[4];
        if (c + 1 < NCHUNK) {
#pragma unroll
            for (int i = 0; i < 4; i++)
                av[i] = *reinterpret_cast<const float4*>(gA + (c + 1) * BKC + i * 4);
            cp_B(c + 1, nstage);
            CP_COMMIT();
        }

        // ---- compute current chunk: 2 k16-steps ----
#pragma unroll
        for (int ks = 0; ks < 2; ks++) {
            const uint32_t ko = ks * 32;
            uint32_t bh[2][4], bl[2][4];
#pragma unroll
            for (int ng = 0; ng < 2; ng++) {
                LDSM4(bh[ng], stage + BH_OFF + b_lm + ng * (16 * LDB) + ko);
                LDSM4(bl[ng], stage + BL_OFF + b_lm + ng * (16 * LDB) + ko);
            }
#pragma unroll
            for (int mt = 0; mt < 4; mt++) {
                uint32_t ah[4], al[4];
                LDSM4(ah, stage + AH_OFF + a_lm + mt * (16 * LDB) + ko);
                LDSM4(al, stage + AL_OFF + a_lm + mt * (16 * LDB) + ko);
#pragma unroll
                for (int nf = 0; nf < 4; nf++)
                    MMA_BF16(acc[mt][nf], ah,
                             bh[nf >> 1][(nf & 1) * 2], bh[nf >> 1][(nf & 1) * 2 + 1]);
#pragma unroll
                for (int nf = 0; nf < 4; nf++)
                    MMA_BF16(acc[mt][nf], ah,
                             bl[nf >> 1][(nf & 1) * 2], bl[nf >> 1][(nf & 1) * 2 + 1]);
#pragma unroll
                for (int nf = 0; nf < 4; nf++)
                    MMA_BF16(acc[mt][nf], al,
                             bh[nf >> 1][(nf & 1) * 2], bh[nf >> 1][(nf & 1) * 2 + 1]);
            }
        }

        if (c + 1 < NCHUNK) {
            store_A(av, nstage);
            CP_WAIT0();
        }
        __syncthreads();
    }

    // ---- epilogue ----
#pragma unroll
    for (int mt = 0; mt < 4; mt++) {
        const int row = m0 + mw * 64 + mt * 16 + (lane >> 2);
#pragma unroll
        for (int nf = 0; nf < 4; nf++) {
            const int col = nw * 32 + nf * 8 + (lane & 3) * 2;
            if (col < K_) {
                float2 v0 = {acc[mt][nf][0], acc[mt][nf][1]};
                float2 v1 = {acc[mt][nf][2], acc[mt][nf][3]};
                *reinterpret_cast<float2*>(out + ((size_t)row * G_ + g) * K_ + col) = v0;
                *reinterpret_cast<float2*>(out + ((size_t)(row + 8) * G_ + g) * K_ + col) = v1;
            }
        }
    }
}

// ---------------------------------------------------------------------------
extern "C" void kernel_launch(void* const* d_in, const int* in_sizes, int n_in,
                              void* d_out, int out_size) {
    const float* h = (const float*)d_in[0];   // [512,100,768]
    const float* w = (const float*)d_in[1];   // [100,768,100]
    float* out = (float*)d_out;               // [512,100,100]
    (void)in_sizes; (void)n_in; (void)out_size;

    const int smem_bytes = 2 * STAGE_BYTES;   // 81920 per CTA -> 2 CTAs/SM
    cudaFuncSetAttribute(gemm_hmma_kernel,
                         cudaFuncAttributeMaxDynamicSharedMemorySize, smem_bytes);

    norm_w_kernel<<<G_, 512>>>(w);
    split_w_kernel<<<dim3(12, G_), 256>>>(w);
    dim3 grid(B_ / 128, G_);
    gemm_hmma_kernel<<<grid, 256, smem_bytes>>>(h, out);
}

// round 11
// speedup vs baseline: 1.1597x; 1.1597x over previous
#include <cuda_runtime.h>
#include <cuda_bf16.h>
#include <cstdint>

// out[b,g,k] = sum_d (h[b,g,d]/||h||) * (w[g,d,k]/||w_col||)
// B=512, G=100, D=768, K=100.
// bf16 two-term split, 3-product HMMA, ldmatrix, double-buffered smem.
// R6 shape (128x128 CTA, 16 warps, warp 32x32, BKC=32, 2 CTAs/SM).
// norm_w parallelized into 400-block partial kernel + combine in split_w.

#define B_ 512
#define G_ 100
#define D_ 768
#define K_ 100
#define KP 128
#define BKC 32              // k-chunk
#define NCHUNK (D_ / BKC)   // 24
#define LDB 80              // smem row stride bytes (32 bf16 + pad)

#define AH_OFF 0
#define AL_OFF 10240
#define BH_OFF 20480
#define BL_OFF 30720
#define STAGE_BYTES 40960

// ---------------- device scratch ----------------
__device__ float g_inv_h[B_ * G_];
__device__ float g_wpart[4 * G_ * 128];     // norm_w partials [seg][g][k]
__device__ __nv_bfloat16 g_wt_hi[(size_t)G_ * KP * D_];   // zero-init (.bss)
__device__ __nv_bfloat16 g_wt_lo[(size_t)G_ * KP * D_];

// ---------------- helpers ----------------
__device__ __forceinline__ uint32_t smem_u32(const void* p) {
    uint32_t a;
    asm("{ .reg .u64 t; cvta.to.shared.u64 t, %1; cvt.u32.u64 %0, t; }"
        : "=r"(a) : "l"(p));
    return a;
}

#define MMA_BF16(d, a, b0, b1)                                              \
    asm volatile(                                                           \
        "mma.sync.aligned.m16n8k16.row.col.f32.bf16.bf16.f32 "              \
        "{%0,%1,%2,%3}, {%4,%5,%6,%7}, {%8,%9}, {%0,%1,%2,%3};"             \
        : "+f"(d[0]), "+f"(d[1]), "+f"(d[2]), "+f"(d[3])                    \
        : "r"(a[0]), "r"(a[1]), "r"(a[2]), "r"(a[3]), "r"(b0), "r"(b1))

#define LDSM4(r, addr)                                                      \
    asm volatile("ldmatrix.sync.aligned.m8n8.x4.shared.b16 "                \
                 "{%0,%1,%2,%3}, [%4];"                                     \
                 : "=r"((r)[0]), "=r"((r)[1]), "=r"((r)[2]), "=r"((r)[3])   \
                 : "r"(addr))

#define CP16(dst, src)                                                      \
    asm volatile("cp.async.cg.shared.global [%0], [%1], 16;"                \
                 :: "r"(dst), "l"(src) : "memory")
#define CP_COMMIT() asm volatile("cp.async.commit_group;" ::: "memory")
#define CP_WAIT0()  asm volatile("cp.async.wait_group 0;" ::: "memory")

// ---------------------------------------------------------------------------
__global__ void norm_h_kernel(const float* __restrict__ h) {
    int warp = (blockIdx.x * blockDim.x + threadIdx.x) >> 5;
    int lane = threadIdx.x & 31;
    if (warp >= B_ * G_) return;
    const float4* p = reinterpret_cast<const float4*>(h + (size_t)warp * D_);
    float s = 0.f;
#pragma unroll
    for (int t = 0; t < 6; t++) {
        float4 v = p[lane + 32 * t];
        s += v.x * v.x + v.y * v.y + v.z * v.z + v.w * v.w;
    }
#pragma unroll
    for (int o = 16; o; o >>= 1) s += __shfl_xor_sync(0xffffffffu, s, o);
    if (lane == 0) g_inv_h[warp] = 1.0f / fmaxf(sqrtf(s), 1e-12f);
}

// ---------------------------------------------------------------------------
// norm_w partials: grid (4 segs, 100 g), 256 threads. Each block sums 192 d.
// ---------------------------------------------------------------------------
__global__ void norm_w_part_kernel(const float* __restrict__ w) {
    __shared__ float part[2][128];
    const int seg = blockIdx.x;            // 0..3
    const int g   = blockIdx.y;
    const int k   = threadIdx.x & 127;
    const int c   = threadIdx.x >> 7;      // 0..1, 96 d each
    float s = 0.f;
    if (k < K_) {
        const float* base = w + (size_t)g * D_ * K_
                              + ((size_t)seg * 192 + (size_t)c * 96) * K_ + k;
#pragma unroll 8
        for (int d = 0; d < 96; d++) {
            float v = base[(size_t)d * K_];
            s += v * v;
        }
    }
    part[c][k] = s;
    __syncthreads();
    if (c == 0)
        g_wpart[((size_t)seg * G_ + g) * 128 + k] = part[0][k] + part[1][k];
}

// ---------------------------------------------------------------------------
// split_w: combine partials -> invw (smem), then normalize/split/transpose.
// grid (12 d-chunks, 100 g), 256 threads. Rows k>=100 never stored (stay 0).
// ---------------------------------------------------------------------------
__global__ void split_w_kernel(const float* __restrict__ w) {
    __shared__ float invw_s[128];
    __shared__ float ws[64][104];
    const int dc = blockIdx.x;
    const int g  = blockIdx.y;
    const int tid = threadIdx.x;

    if (tid < 128) {
        float s = g_wpart[((size_t)0 * G_ + g) * 128 + tid]
                + g_wpart[((size_t)1 * G_ + g) * 128 + tid]
                + g_wpart[((size_t)2 * G_ + g) * 128 + tid]
                + g_wpart[((size_t)3 * G_ + g) * 128 + tid];
        invw_s[tid] = (tid < K_) ? 1.0f / fmaxf(sqrtf(s), 1e-12f) : 0.f;
    }

    const float* src = w + (size_t)g * D_ * K_ + (size_t)dc * 64 * K_;
#pragma unroll
    for (int i = 0; i < 25; i++) {
        int idx = tid + 256 * i;
        ws[idx / K_][idx % K_] = src[idx];
    }
    __syncthreads();

    const int k  = tid >> 1;
    if (k >= K_) return;                    // rows 100..127 stay zero (.bss)
    const int d0 = (tid & 1) * 32;
    const float invw = invw_s[k];
    __nv_bfloat16 hb[32], lb[32];
#pragma unroll
    for (int j = 0; j < 32; j++) {
        float x = ws[d0 + j][k] * invw;
        __nv_bfloat16 hi = __float2bfloat16(x);
        hb[j] = hi;
        lb[j] = __float2bfloat16(x - __bfloat162float(hi));
    }
    size_t base = ((size_t)g * KP + k) * D_ + (size_t)dc * 64 + d0;
    uint4* dh = reinterpret_cast<uint4*>(g_wt_hi + base);
    uint4* dl = reinterpret_cast<uint4*>(g_wt_lo + base);
#pragma unroll
    for (int q = 0; q < 4; q++) {
        dh[q] = *reinterpret_cast<const uint4*>(hb + q * 8);
        dl[q] = *reinterpret_cast<const uint4*>(lb + q * 8);
    }
}

// ---------------------------------------------------------------------------
// HMMA GEMM (R6, unchanged). CTA = (g, 128 rows), 16 warps: mw = warp&3,
// nw = warp>>2. Warp tile 32x32, 3 bf16 products, fp32 acc. 2 CTAs/SM.
// ---------------------------------------------------------------------------
__global__ __launch_bounds__(256, 2)
void gemm_hmma_kernel(const float* __restrict__ h, float* __restrict__ out) {
    extern __shared__ char smem[];
    const uint32_t sb = smem_u32(smem);
    const int tid  = threadIdx.x;
    const int lane = tid & 31;
    const int warp = tid >> 5;
    const int mw = warp & 1;
    const int nw = warp >> 1;
    const int g  = blockIdx.y;
    const int m0 = blockIdx.x * 128;

    // ---- global load mapping: 2 threads per row, 16 elems each ----
    const int arow = tid >> 1;
    const int half = tid & 1;
    const float* gA = h + ((size_t)(m0 + arow) * G_ + g) * D_ + half * 16;
    const float invh = g_inv_h[(size_t)(m0 + arow) * G_ + g];
    const char* gBh = reinterpret_cast<const char*>(
        g_wt_hi + ((size_t)g * KP + arow) * D_) + half * 32;
    const char* gBl = reinterpret_cast<const char*>(
        g_wt_lo + ((size_t)g * KP + arow) * D_) + half * 32;

    const uint32_t srow = arow * LDB + half * 32;

    // ldmatrix base addresses (stage-relative)
    const uint32_t a_lm = (mw * 64 + (lane & 15)) * LDB + (lane >> 4) * 16;
    const uint32_t b_lm = (nw * 32 + (lane & 7) + ((lane >> 4) & 1) * 8) * LDB
                        + ((lane >> 3) & 1) * 16;

    float acc[4][4][4];   // [mt][nf][reg]
#pragma unroll
    for (int mt = 0; mt < 4; mt++)
#pragma unroll
        for (int nf = 0; nf < 4; nf++)
#pragma unroll
            for (int r = 0; r < 4; r++) acc[mt][nf][r] = 0.f;

    // ---- A convert+store: 16 fp32 -> hi/lo bf16 (32B each) ----
    auto store_A = [&](const float4* av, uint32_t stage) {
        uint32_t uh[8], ul[8];
#pragma unroll
        for (int i = 0; i < 4; i++) {
            float x0 = av[i].x * invh, x1 = av[i].y * invh;
            float x2 = av[i].z * invh, x3 = av[i].w * invh;
            __nv_bfloat162 h0 = __float22bfloat162_rn(make_float2(x0, x1));
            __nv_bfloat162 h1 = __float22bfloat162_rn(make_float2(x2, x3));
            float2 f0 = __bfloat1622float2(h0), f1 = __bfloat1622float2(h1);
            __nv_bfloat162 l0 = __float22bfloat162_rn(make_float2(x0 - f0.x, x1 - f0.y));
            __nv_bfloat162 l1 = __float22bfloat162_rn(make_float2(x2 - f1.x, x3 - f1.y));
            uh[i * 2]     = *reinterpret_cast<uint32_t*>(&h0);
            uh[i * 2 + 1] = *reinterpret_cast<uint32_t*>(&h1);
            ul[i * 2]     = *reinterpret_cast<uint32_t*>(&l0);
            ul[i * 2 + 1] = *reinterpret_cast<uint32_t*>(&l1);
        }
        asm volatile("st.shared.v4.b32 [%0], {%1,%2,%3,%4};"
            :: "r"(stage + AH_OFF + srow), "r"(uh[0]), "r"(uh[1]), "r"(uh[2]), "r"(uh[3]) : "memory");
        asm volatile("st.shared.v4.b32 [%0], {%1,%2,%3,%4};"
            :: "r"(stage + AH_OFF + srow + 16), "r"(uh[4]), "r"(uh[5]), "r"(uh[6]), "r"(uh[7]) : "memory");
        asm volatile("st.shared.v4.b32 [%0], {%1,%2,%3,%4};"
            :: "r"(stage + AL_OFF + srow), "r"(ul[0]), "r"(ul[1]), "r"(ul[2]), "r"(ul[3]) : "memory");
        asm volatile("st.shared.v4.b32 [%0], {%1,%2,%3,%4};"
            :: "r"(stage + AL_OFF + srow + 16), "r"(ul[4]), "r"(ul[5]), "r"(ul[6]), "r"(ul[7]) : "memory");
    };

    auto cp_B = [&](int c, uint32_t stage) {
        CP16(stage + BH_OFF + srow,      gBh + (size_t)c * 64);
        CP16(stage + BH_OFF + srow + 16, gBh + (size_t)c * 64 + 16);
        CP16(stage + BL_OFF + srow,      gBl + (size_t)c * 64);
        CP16(stage + BL_OFF + srow + 16, gBl + (size_t)c * 64 + 16);
    };

    // ---- prologue: fill stage 0 ----
    {
        float4 av[4];
#pragma unroll
        for (int i = 0; i < 4; i++)
            av[i] = *reinterpret_cast<const float4*>(gA + i * 4);
        cp_B(0, sb);
        CP_COMMIT();
        store_A(av, sb);
        CP_WAIT0();
    }
    __syncthreads();

    for (int c = 0; c < NCHUNK; c++) {
        const uint32_t stage  = sb + (uint32_t)(c & 1) * STAGE_BYTES;
        const uint32_t nstage = sb + (uint32_t)((c + 1) & 1) * STAGE_BYTES;

        float4 av[4];
        if (c + 1 < NCHUNK) {
#pragma unroll
            for (int i = 0; i < 4; i++)
                av[i] = *reinterpret_cast<const float4*>(gA + (c + 1) * BKC + i * 4);
            cp_B(c + 1, nstage);
            CP_COMMIT();
        }

        // ---- compute current chunk: 2 k16-steps ----
#pragma unroll
        for (int ks = 0; ks < 2; ks++) {
            const uint32_t ko = ks * 32;
            uint32_t bh[2][4], bl[2][4];
#pragma unroll
            for (int ng = 0; ng < 2; ng++) {
                LDSM4(bh[ng], stage + BH_OFF + b_lm + ng * (16 * LDB) + ko);
                LDSM4(bl[ng], stage + BL_OFF + b_lm + ng * (16 * LDB) + ko);
            }
#pragma unroll
            for (int mt = 0; mt < 4; mt++) {
                uint32_t ah[4], al[4];
                LDSM4(ah, stage + AH_OFF + a_lm + mt * (16 * LDB) + ko);
                LDSM4(al, stage + AL_OFF + a_lm + mt * (16 * LDB) + ko);
#pragma unroll
                for (int nf = 0; nf < 4; nf++)
                    MMA_BF16(acc[mt][nf], ah,
                             bh[nf >> 1][(nf & 1) * 2], bh[nf >> 1][(nf & 1) * 2 + 1]);
#pragma unroll
                for (int nf = 0; nf < 4; nf++)
                    MMA_BF16(acc[mt][nf], ah,
                             bl[nf >> 1][(nf & 1) * 2], bl[nf >> 1][(nf & 1) * 2 + 1]);
#pragma unroll
                for (int nf = 0; nf < 4; nf++)
                    MMA_BF16(acc[mt][nf], al,
                             bh[nf >> 1][(nf & 1) * 2], bh[nf >> 1][(nf & 1) * 2 + 1]);
            }
        }

        if (c + 1 < NCHUNK) {
            store_A(av, nstage);
            CP_WAIT0();
        }
        __syncthreads();
    }

    // ---- epilogue ----
#pragma unroll
    for (int mt = 0; mt < 4; mt++) {
        const int row = m0 + mw * 64 + mt * 16 + (lane >> 2);
#pragma unroll
        for (int nf = 0; nf < 4; nf++) {
            const int col = nw * 32 + nf * 8 + (lane & 3) * 2;
            if (col < K_) {
                float2 v0 = {acc[mt][nf][0], acc[mt][nf][1]};
                float2 v1 = {acc[mt][nf][2], acc[mt][nf][3]};
                *reinterpret_cast<float2*>(out + ((size_t)row * G_ + g) * K_ + col) = v0;
                *reinterpret_cast<float2*>(out + ((size_t)(row + 8) * G_ + g) * K_ + col) = v1;
            }
        }
    }
}

// ---------------------------------------------------------------------------
extern "C" void kernel_launch(void* const* d_in, const int* in_sizes, int n_in,
                              void* d_out, int out_size) {
    const float* h = (const float*)d_in[0];   // [512,100,768]
    const float* w = (const float*)d_in[1];   // [100,768,100]
    float* out = (float*)d_out;               // [512,100,100]
    (void)in_sizes; (void)n_in; (void)out_size;

    const int smem_bytes = 2 * STAGE_BYTES;   // 81920 per CTA -> 2 CTAs/SM
    cudaFuncSetAttribute(gemm_hmma_kernel,
                         cudaFuncAttributeMaxDynamicSharedMemorySize, smem_bytes);

    norm_h_kernel<<<(B_ * G_) / 8, 256>>>(h);
    norm_w_part_kernel<<<dim3(4, G_), 256>>>(w);
    split_w_kernel<<<dim3(12, G_), 256>>>(w);
    dim3 grid(B_ / 128, G_);
    gemm_hmma_kernel<<<grid, 256, smem_bytes>>>(h, out);
}

// round 12
// speedup vs baseline: 1.3677x; 1.1793x over previous
#include <cuda_runtime.h>
#include <cuda_bf16.h>
#include <cstdint>

// out[b,g,k] = sum_d (h[b,g,d]/||h||) * (w[g,d,k]/||w_col||)
// B=512, G=100, D=768, K=100.
// bf16 two-term split, 3-product HMMA, ldmatrix, double-buffered smem.
// R6 GEMM shape (128x128 CTA, 8 warps, warp 64x32, BKC=32, 2 CTAs/SM).
// invw folded into B scratch; invh computed INSIDE the GEMM (sumsq during
// A conversion, applied in epilogue) -> norm_h kernel eliminated.

#define B_ 512
#define G_ 100
#define D_ 768
#define K_ 100
#define KP 128
#define BKC 32              // k-chunk
#define NCHUNK (D_ / BKC)   // 24
#define LDB 80              // smem row stride bytes (32 bf16 + pad)

#define AH_OFF 0
#define AL_OFF 10240
#define BH_OFF 20480
#define BL_OFF 30720
#define STAGE_BYTES 40960

// ---------------- device scratch ----------------
__device__ float g_wpart[4 * G_ * 128];     // norm_w partials [seg][g][k]
__device__ __nv_bfloat16 g_wt_hi[(size_t)G_ * KP * D_];   // zero-init (.bss)
__device__ __nv_bfloat16 g_wt_lo[(size_t)G_ * KP * D_];

// ---------------- helpers ----------------
__device__ __forceinline__ uint32_t smem_u32(const void* p) {
    uint32_t a;
    asm("{ .reg .u64 t; cvta.to.shared.u64 t, %1; cvt.u32.u64 %0, t; }"
        : "=r"(a) : "l"(p));
    return a;
}

#define MMA_BF16(d, a, b0, b1)                                              \
    asm volatile(                                                           \
        "mma.sync.aligned.m16n8k16.row.col.f32.bf16.bf16.f32 "              \
        "{%0,%1,%2,%3}, {%4,%5,%6,%7}, {%8,%9}, {%0,%1,%2,%3};"             \
        : "+f"(d[0]), "+f"(d[1]), "+f"(d[2]), "+f"(d[3])                    \
        : "r"(a[0]), "r"(a[1]), "r"(a[2]), "r"(a[3]), "r"(b0), "r"(b1))

#define LDSM4(r, addr)                                                      \
    asm volatile("ldmatrix.sync.aligned.m8n8.x4.shared.b16 "                \
                 "{%0,%1,%2,%3}, [%4];"                                     \
                 : "=r"((r)[0]), "=r"((r)[1]), "=r"((r)[2]), "=r"((r)[3])   \
                 : "r"(addr))

#define CP16(dst, src)                                                      \
    asm volatile("cp.async.cg.shared.global [%0], [%1], 16;"                \
                 :: "r"(dst), "l"(src) : "memory")
#define CP_COMMIT() asm volatile("cp.async.commit_group;" ::: "memory")
#define CP_WAIT0()  asm volatile("cp.async.wait_group 0;" ::: "memory")

// ---------------------------------------------------------------------------
// norm_w partials: grid (4 segs, 100 g), 256 threads. Each block sums 192 d.
// ---------------------------------------------------------------------------
__global__ void norm_w_part_kernel(const float* __restrict__ w) {
    __shared__ float part[2][128];
    const int seg = blockIdx.x;            // 0..3
    const int g   = blockIdx.y;
    const int k   = threadIdx.x & 127;
    const int c   = threadIdx.x >> 7;      // 0..1, 96 d each
    float s = 0.f;
    if (k < K_) {
        const float* base = w + (size_t)g * D_ * K_
                              + ((size_t)seg * 192 + (size_t)c * 96) * K_ + k;
#pragma unroll 8
        for (int d = 0; d < 96; d++) {
            float v = base[(size_t)d * K_];
            s += v * v;
        }
    }
    part[c][k] = s;
    __syncthreads();
    if (c == 0)
        g_wpart[((size_t)seg * G_ + g) * 128 + k] = part[0][k] + part[1][k];
}

// ---------------------------------------------------------------------------
// split_w: combine partials -> invw (smem), then normalize/split/transpose.
// grid (12 d-chunks, 100 g), 256 threads. Rows k>=100 never stored (stay 0).
// ---------------------------------------------------------------------------
__global__ void split_w_kernel(const float* __restrict__ w) {
    __shared__ float invw_s[128];
    __shared__ float ws[64][104];
    const int dc = blockIdx.x;
    const int g  = blockIdx.y;
    const int tid = threadIdx.x;

    if (tid < 128) {
        float s = g_wpart[((size_t)0 * G_ + g) * 128 + tid]
                + g_wpart[((size_t)1 * G_ + g) * 128 + tid]
                + g_wpart[((size_t)2 * G_ + g) * 128 + tid]
                + g_wpart[((size_t)3 * G_ + g) * 128 + tid];
        invw_s[tid] = (tid < K_) ? 1.0f / fmaxf(sqrtf(s), 1e-12f) : 0.f;
    }

    const float* src = w + (size_t)g * D_ * K_ + (size_t)dc * 64 * K_;
#pragma unroll
    for (int i = 0; i < 25; i++) {
        int idx = tid + 256 * i;
        ws[idx / K_][idx % K_] = src[idx];
    }
    __syncthreads();

    const int k  = tid >> 1;
    if (k >= K_) return;                    // rows 100..127 stay zero (.bss)
    const int d0 = (tid & 1) * 32;
    const float invw = invw_s[k];
    __nv_bfloat16 hb[32], lb[32];
#pragma unroll
    for (int j = 0; j < 32; j++) {
        float x = ws[d0 + j][k] * invw;
        __nv_bfloat16 hi = __float2bfloat16(x);
        hb[j] = hi;
        lb[j] = __float2bfloat16(x - __bfloat162float(hi));
    }
    size_t base = ((size_t)g * KP + k) * D_ + (size_t)dc * 64 + d0;
    uint4* dh = reinterpret_cast<uint4*>(g_wt_hi + base);
    uint4* dl = reinterpret_cast<uint4*>(g_wt_lo + base);
#pragma unroll
    for (int q = 0; q < 4; q++) {
        dh[q] = *reinterpret_cast<const uint4*>(hb + q * 8);
        dl[q] = *reinterpret_cast<const uint4*>(lb + q * 8);
    }
}

// ---------------------------------------------------------------------------
// HMMA GEMM. CTA = (g, 128 rows), 8 warps: mw = warp&1 (64 rows),
// nw = warp>>1 (32 cols). Warp tile 64x32, 3 bf16 products, fp32 acc.
// A split WITHOUT pre-normalization; row sumsq accumulated during convert;
// invh applied in epilogue (scale-commuted, same accuracy).
// ---------------------------------------------------------------------------
__global__ __launch_bounds__(256, 2)
void gemm_hmma_kernel(const float* __restrict__ h, float* __restrict__ out) {
    extern __shared__ char smem[];
    const uint32_t sb = smem_u32(smem);
    const int tid  = threadIdx.x;
    const int lane = tid & 31;
    const int warp = tid >> 5;
    const int mw = warp & 1;
    const int nw = warp >> 1;
    const int g  = blockIdx.y;
    const int m0 = blockIdx.x * 128;

    // ---- global load mapping: 2 threads per row, 16 elems each ----
    const int arow = tid >> 1;
    const int half = tid & 1;
    const float* gA = h + ((size_t)(m0 + arow) * G_ + g) * D_ + half * 16;
    const char* gBh = reinterpret_cast<const char*>(
        g_wt_hi + ((size_t)g * KP + arow) * D_) + half * 32;
    const char* gBl = reinterpret_cast<const char*>(
        g_wt_lo + ((size_t)g * KP + arow) * D_) + half * 32;

    const uint32_t srow = arow * LDB + half * 32;

    // ldmatrix base addresses (stage-relative)
    const uint32_t a_lm = (mw * 64 + (lane & 15)) * LDB + (lane >> 4) * 16;
    const uint32_t b_lm = (nw * 32 + (lane & 7) + ((lane >> 4) & 1) * 8) * LDB
                        + ((lane >> 3) & 1) * 16;

    float acc[4][4][4];   // [mt][nf][reg]
#pragma unroll
    for (int mt = 0; mt < 4; mt++)
#pragma unroll
        for (int nf = 0; nf < 4; nf++)
#pragma unroll
            for (int r = 0; r < 4; r++) acc[mt][nf][r] = 0.f;

    float sumsq = 0.f;    // this thread's half-row sum of squares

    // ---- A convert+store: 16 fp32 -> hi/lo bf16, accumulate sumsq ----
    auto store_A = [&](const float4* av, uint32_t stage) {
        uint32_t uh[8], ul[8];
#pragma unroll
        for (int i = 0; i < 4; i++) {
            float x0 = av[i].x, x1 = av[i].y, x2 = av[i].z, x3 = av[i].w;
            sumsq = fmaf(x0, x0, sumsq);
            sumsq = fmaf(x1, x1, sumsq);
            sumsq = fmaf(x2, x2, sumsq);
            sumsq = fmaf(x3, x3, sumsq);
            __nv_bfloat162 h0 = __float22bfloat162_rn(make_float2(x0, x1));
            __nv_bfloat162 h1 = __float22bfloat162_rn(make_float2(x2, x3));
            float2 f0 = __bfloat1622float2(h0), f1 = __bfloat1622float2(h1);
            __nv_bfloat162 l0 = __float22bfloat162_rn(make_float2(x0 - f0.x, x1 - f0.y));
            __nv_bfloat162 l1 = __float22bfloat162_rn(make_float2(x2 - f1.x, x3 - f1.y));
            uh[i * 2]     = *reinterpret_cast<uint32_t*>(&h0);
            uh[i * 2 + 1] = *reinterpret_cast<uint32_t*>(&h1);
            ul[i * 2]     = *reinterpret_cast<uint32_t*>(&l0);
            ul[i * 2 + 1] = *reinterpret_cast<uint32_t*>(&l1);
        }
        asm volatile("st.shared.v4.b32 [%0], {%1,%2,%3,%4};"
            :: "r"(stage + AH_OFF + srow), "r"(uh[0]), "r"(uh[1]), "r"(uh[2]), "r"(uh[3]) : "memory");
        asm volatile("st.shared.v4.b32 [%0], {%1,%2,%3,%4};"
            :: "r"(stage + AH_OFF + srow + 16), "r"(uh[4]), "r"(uh[5]), "r"(uh[6]), "r"(uh[7]) : "memory");
        asm volatile("st.shared.v4.b32 [%0], {%1,%2,%3,%4};"
            :: "r"(stage + AL_OFF + srow), "r"(ul[0]), "r"(ul[1]), "r"(ul[2]), "r"(ul[3]) : "memory");
        asm volatile("st.shared.v4.b32 [%0], {%1,%2,%3,%4};"
            :: "r"(stage + AL_OFF + srow + 16), "r"(ul[4]), "r"(ul[5]), "r"(ul[6]), "r"(ul[7]) : "memory");
    };

    auto cp_B = [&](int c, uint32_t stage) {
        CP16(stage + BH_OFF + srow,      gBh + (size_t)c * 64);
        CP16(stage + BH_OFF + srow + 16, gBh + (size_t)c * 64 + 16);
        CP16(stage + BL_OFF + srow,      gBl + (size_t)c * 64);
        CP16(stage + BL_OFF + srow + 16, gBl + (size_t)c * 64 + 16);
    };

    // ---- prologue: fill stage 0 ----
    {
        float4 av[4];
#pragma unroll
        for (int i = 0; i < 4; i++)
            av[i] = *reinterpret_cast<const float4*>(gA + i * 4);
        cp_B(0, sb);
        CP_COMMIT();
        store_A(av, sb);
        CP_WAIT0();
    }
    __syncthreads();

    for (int c = 0; c < NCHUNK; c++) {
        const uint32_t stage  = sb + (uint32_t)(c & 1) * STAGE_BYTES;
        const uint32_t nstage = sb + (uint32_t)((c + 1) & 1) * STAGE_BYTES;

        float4 av[4];
        if (c + 1 < NCHUNK) {
#pragma unroll
            for (int i = 0; i < 4; i++)
                av[i] = *reinterpret_cast<const float4*>(gA + (c + 1) * BKC + i * 4);
            cp_B(c + 1, nstage);
            CP_COMMIT();
        }

        // ---- compute current chunk: 2 k16-steps ----
#pragma unroll
        for (int ks = 0; ks < 2; ks++) {
            const uint32_t ko = ks * 32;
            uint32_t bh[2][4], bl[2][4];
#pragma unroll
            for (int ng = 0; ng < 2; ng++) {
                LDSM4(bh[ng], stage + BH_OFF + b_lm + ng * (16 * LDB) + ko);
                LDSM4(bl[ng], stage + BL_OFF + b_lm + ng * (16 * LDB) + ko);
            }
#pragma unroll
            for (int mt = 0; mt < 4; mt++) {
                uint32_t ah[4], al[4];
                LDSM4(ah, stage + AH_OFF + a_lm + mt * (16 * LDB) + ko);
                LDSM4(al, stage + AL_OFF + a_lm + mt * (16 * LDB) + ko);
#pragma unroll
                for (int nf = 0; nf < 4; nf++)
                    MMA_BF16(acc[mt][nf], ah,
                             bh[nf >> 1][(nf & 1) * 2], bh[nf >> 1][(nf & 1) * 2 + 1]);
#pragma unroll
                for (int nf = 0; nf < 4; nf++)
                    MMA_BF16(acc[mt][nf], ah,
                             bl[nf >> 1][(nf & 1) * 2], bl[nf >> 1][(nf & 1) * 2 + 1]);
#pragma unroll
                for (int nf = 0; nf < 4; nf++)
                    MMA_BF16(acc[mt][nf], al,
                             bh[nf >> 1][(nf & 1) * 2], bh[nf >> 1][(nf & 1) * 2 + 1]);
            }
        }

        if (c + 1 < NCHUNK) {
            store_A(av, nstage);
            CP_WAIT0();
        }
        __syncthreads();
    }

    // ---- row-norm exchange: combine halves, publish to smem ----
    sumsq += __shfl_xor_sync(0xffffffffu, sumsq, 1);
    float* rowsq = reinterpret_cast<float*>(smem);
    if (half == 0) rowsq[arow] = sumsq;
    __syncthreads();

    // ---- epilogue: scale by invh, store ----
#pragma unroll
    for (int mt = 0; mt < 4; mt++) {
        const int rl = mw * 64 + mt * 16 + (lane >> 2);
        const float ih0 = 1.0f / fmaxf(sqrtf(rowsq[rl]), 1e-12f);
        const float ih1 = 1.0f / fmaxf(sqrtf(rowsq[rl + 8]), 1e-12f);
        const int row = m0 + rl;
#pragma unroll
        for (int nf = 0; nf < 4; nf++) {
            const int col = nw * 32 + nf * 8 + (lane & 3) * 2;
            if (col < K_) {
                float2 v0 = {acc[mt][nf][0] * ih0, acc[mt][nf][1] * ih0};
                float2 v1 = {acc[mt][nf][2] * ih1, acc[mt][nf][3] * ih1};
                *reinterpret_cast<float2*>(out + ((size_t)row * G_ + g) * K_ + col) = v0;
                *reinterpret_cast<float2*>(out + ((size_t)(row + 8) * G_ + g) * K_ + col) = v1;
            }
        }
    }
}

// ---------------------------------------------------------------------------
extern "C" void kernel_launch(void* const* d_in, const int* in_sizes, int n_in,
                              void* d_out, int out_size) {
    const float* h = (const float*)d_in[0];   // [512,100,768]
    const float* w = (const float*)d_in[1];   // [100,768,100]
    float* out = (float*)d_out;               // [512,100,100]
    (void)in_sizes; (void)n_in; (void)out_size;

    const int smem_bytes = 2 * STAGE_BYTES;   // 81920 per CTA -> 2 CTAs/SM
    cudaFuncSetAttribute(gemm_hmma_kernel,
                         cudaFuncAttributeMaxDynamicSharedMemorySize, smem_bytes);

    norm_w_part_kernel<<<dim3(4, G_), 256>>>(w);
    split_w_kernel<<<dim3(12, G_), 256>>>(w);
    dim3 grid(B_ / 128, G_);
    gemm_hmma_kernel<<<grid, 256, smem_bytes>>>(h, out);
}

// round 13
// speedup vs baseline: 1.4094x; 1.0305x over previous
#include <cuda_runtime.h>
#include <cuda_bf16.h>
#include <cstdint>

// out[b,g,k] = sum_d (h[b,g,d]/||h||) * (w[g,d,k]/||w_col||)
// B=512, G=100, D=768, K=100.
// bf16 two-term split, 3-product HMMA, ldmatrix, double-buffered smem.
// R6 GEMM shape (128x128 CTA, 8 warps, warp 64x32, BKC=32, 2 CTAs/SM).
// BOTH norms commuted into the GEMM epilogue:
//   invh computed inside the GEMM (sumsq during A-convert),
//   invw from a tiny table; w split UNNORMALIZED -> norm and split kernels
//   are independent and fused into one launch.

#define B_ 512
#define G_ 100
#define D_ 768
#define K_ 100
#define KP 128
#define BKC 32              // k-chunk
#define NCHUNK (D_ / BKC)   // 24
#define LDB 80              // smem row stride bytes (32 bf16 + pad)

#define AH_OFF 0
#define AL_OFF 10240
#define BH_OFF 20480
#define BL_OFF 30720
#define STAGE_BYTES 40960

// ---------------- device scratch ----------------
__device__ float g_wpart[4 * G_ * 128];     // norm_w partials [seg][g][k]
__device__ float g_inv_w2[G_ * 128];        // invw table [g][k] (0 for k>=100)
__device__ __nv_bfloat16 g_wt_hi[(size_t)G_ * KP * D_];   // zero-init (.bss)
__device__ __nv_bfloat16 g_wt_lo[(size_t)G_ * KP * D_];

// ---------------- helpers ----------------
__device__ __forceinline__ uint32_t smem_u32(const void* p) {
    uint32_t a;
    asm("{ .reg .u64 t; cvta.to.shared.u64 t, %1; cvt.u32.u64 %0, t; }"
        : "=r"(a) : "l"(p));
    return a;
}

#define MMA_BF16(d, a, b0, b1)                                              \
    asm volatile(                                                           \
        "mma.sync.aligned.m16n8k16.row.col.f32.bf16.bf16.f32 "              \
        "{%0,%1,%2,%3}, {%4,%5,%6,%7}, {%8,%9}, {%0,%1,%2,%3};"             \
        : "+f"(d[0]), "+f"(d[1]), "+f"(d[2]), "+f"(d[3])                    \
        : "r"(a[0]), "r"(a[1]), "r"(a[2]), "r"(a[3]), "r"(b0), "r"(b1))

#define LDSM4(r, addr)                                                      \
    asm volatile("ldmatrix.sync.aligned.m8n8.x4.shared.b16 "                \
                 "{%0,%1,%2,%3}, [%4];"                                     \
                 : "=r"((r)[0]), "=r"((r)[1]), "=r"((r)[2]), "=r"((r)[3])   \
                 : "r"(addr))

#define CP16(dst, src)                                                      \
    asm volatile("cp.async.cg.shared.global [%0], [%1], 16;"                \
                 :: "r"(dst), "l"(src) : "memory")
#define CP_COMMIT() asm volatile("cp.async.commit_group;" ::: "memory")
#define CP_WAIT0()  asm volatile("cp.async.wait_group 0;" ::: "memory")

// ---------------------------------------------------------------------------
// Fused W prep: grid (16, 100), 256 threads.
//   blocks 0..3  : norm partials (seg = bz), each sums 192 d's.
//   blocks 4..15 : split+transpose chunk dc = bz-4 (UNNORMALIZED bf16 hi/lo).
// The two works are independent -> full-machine occupancy in one launch.
// ---------------------------------------------------------------------------
__global__ void prep_w_kernel(const float* __restrict__ w) {
    __shared__ float part[2][128];
    __shared__ float ws[64][104];
    const int bz  = blockIdx.x;
    const int g   = blockIdx.y;
    const int tid = threadIdx.x;

    if (bz < 4) {
        // ---- norm partial ----
        const int seg = bz;
        const int k   = tid & 127;
        const int c   = tid >> 7;            // 0..1, 96 d each
        float s = 0.f;
        if (k < K_) {
            const float* base = w + (size_t)g * D_ * K_
                                  + ((size_t)seg * 192 + (size_t)c * 96) * K_ + k;
#pragma unroll 8
            for (int d = 0; d < 96; d++) {
                float v = base[(size_t)d * K_];
                s += v * v;
            }
        }
        part[c][k] = s;
        __syncthreads();
        if (c == 0)
            g_wpart[((size_t)seg * G_ + g) * 128 + k] = part[0][k] + part[1][k];
        return;
    }

    // ---- split + transpose (no normalization) ----
    const int dc = bz - 4;
    const float* src = w + (size_t)g * D_ * K_ + (size_t)dc * 64 * K_;
#pragma unroll
    for (int i = 0; i < 25; i++) {
        int idx = tid + 256 * i;
        ws[idx / K_][idx % K_] = src[idx];
    }
    __syncthreads();

    const int k = tid >> 1;
    if (k >= K_) return;                     // rows 100..127 stay zero (.bss)
    const int d0 = (tid & 1) * 32;
    __nv_bfloat16 hb[32], lb[32];
#pragma unroll
    for (int j = 0; j < 32; j++) {
        float x = ws[d0 + j][k];
        __nv_bfloat16 hi = __float2bfloat16(x);
        hb[j] = hi;
        lb[j] = __float2bfloat16(x - __bfloat162float(hi));
    }
    size_t base = ((size_t)g * KP + k) * D_ + (size_t)dc * 64 + d0;
    uint4* dh = reinterpret_cast<uint4*>(g_wt_hi + base);
    uint4* dl = reinterpret_cast<uint4*>(g_wt_lo + base);
#pragma unroll
    for (int q = 0; q < 4; q++) {
        dh[q] = *reinterpret_cast<const uint4*>(hb + q * 8);
        dl[q] = *reinterpret_cast<const uint4*>(lb + q * 8);
    }
}

// ---------------------------------------------------------------------------
// combine: invw table from partials. 100 blocks x 128 threads.
// ---------------------------------------------------------------------------
__global__ void combine_w_kernel() {
    const int g = blockIdx.x;
    const int k = threadIdx.x;
    float s = g_wpart[((size_t)0 * G_ + g) * 128 + k]
            + g_wpart[((size_t)1 * G_ + g) * 128 + k]
            + g_wpart[((size_t)2 * G_ + g) * 128 + k]
            + g_wpart[((size_t)3 * G_ + g) * 128 + k];
    g_inv_w2[g * 128 + k] = (k < K_) ? 1.0f / fmaxf(sqrtf(s), 1e-12f) : 0.f;
}

// ---------------------------------------------------------------------------
// HMMA GEMM. CTA = (g, 128 rows), 8 warps: mw = warp&1 (64 rows),
// nw = warp>>1 (32 cols). Warp tile 64x32, 3 bf16 products, fp32 acc.
// A split raw; row sumsq during convert; invh AND invw applied in epilogue.
// ---------------------------------------------------------------------------
__global__ __launch_bounds__(256, 2)
void gemm_hmma_kernel(const float* __restrict__ h, float* __restrict__ out) {
    extern __shared__ char smem[];
    const uint32_t sb = smem_u32(smem);
    const int tid  = threadIdx.x;
    const int lane = tid & 31;
    const int warp = tid >> 5;
    const int mw = warp & 1;
    const int nw = warp >> 1;
    const int g  = blockIdx.y;
    const int m0 = blockIdx.x * 128;

    // ---- global load mapping: 2 threads per row, 16 elems each ----
    const int arow = tid >> 1;
    const int half = tid & 1;
    const float* gA = h + ((size_t)(m0 + arow) * G_ + g) * D_ + half * 16;
    const char* gBh = reinterpret_cast<const char*>(
        g_wt_hi + ((size_t)g * KP + arow) * D_) + half * 32;
    const char* gBl = reinterpret_cast<const char*>(
        g_wt_lo + ((size_t)g * KP + arow) * D_) + half * 32;

    const uint32_t srow = arow * LDB + half * 32;

    // ldmatrix base addresses (stage-relative)
    const uint32_t a_lm = (mw * 64 + (lane & 15)) * LDB + (lane >> 4) * 16;
    const uint32_t b_lm = (nw * 32 + (lane & 7) + ((lane >> 4) & 1) * 8) * LDB
                        + ((lane >> 3) & 1) * 16;

    float acc[4][4][4];   // [mt][nf][reg]
#pragma unroll
    for (int mt = 0; mt < 4; mt++)
#pragma unroll
        for (int nf = 0; nf < 4; nf++)
#pragma unroll
            for (int r = 0; r < 4; r++) acc[mt][nf][r] = 0.f;

    float sumsq = 0.f;    // this thread's half-row sum of squares

    // ---- A convert+store: 16 fp32 -> hi/lo bf16, accumulate sumsq ----
    auto store_A = [&](const float4* av, uint32_t stage) {
        uint32_t uh[8], ul[8];
#pragma unroll
        for (int i = 0; i < 4; i++) {
            float x0 = av[i].x, x1 = av[i].y, x2 = av[i].z, x3 = av[i].w;
            sumsq = fmaf(x0, x0, sumsq);
            sumsq = fmaf(x1, x1, sumsq);
            sumsq = fmaf(x2, x2, sumsq);
            sumsq = fmaf(x3, x3, sumsq);
            __nv_bfloat162 h0 = __float22bfloat162_rn(make_float2(x0, x1));
            __nv_bfloat162 h1 = __float22bfloat162_rn(make_float2(x2, x3));
            float2 f0 = __bfloat1622float2(h0), f1 = __bfloat1622float2(h1);
            __nv_bfloat162 l0 = __float22bfloat162_rn(make_float2(x0 - f0.x, x1 - f0.y));
            __nv_bfloat162 l1 = __float22bfloat162_rn(make_float2(x2 - f1.x, x3 - f1.y));
            uh[i * 2]     = *reinterpret_cast<uint32_t*>(&h0);
            uh[i * 2 + 1] = *reinterpret_cast<uint32_t*>(&h1);
            ul[i * 2]     = *reinterpret_cast<uint32_t*>(&l0);
            ul[i * 2 + 1] = *reinterpret_cast<uint32_t*>(&l1);
        }
        asm volatile("st.shared.v4.b32 [%0], {%1,%2,%3,%4};"
            :: "r"(stage + AH_OFF + srow), "r"(uh[0]), "r"(uh[1]), "r"(uh[2]), "r"(uh[3]) : "memory");
        asm volatile("st.shared.v4.b32 [%0], {%1,%2,%3,%4};"
            :: "r"(stage + AH_OFF + srow + 16), "r"(uh[4]), "r"(uh[5]), "r"(uh[6]), "r"(uh[7]) : "memory");
        asm volatile("st.shared.v4.b32 [%0], {%1,%2,%3,%4};"
            :: "r"(stage + AL_OFF + srow), "r"(ul[0]), "r"(ul[1]), "r"(ul[2]), "r"(ul[3]) : "memory");
        asm volatile("st.shared.v4.b32 [%0], {%1,%2,%3,%4};"
            :: "r"(stage + AL_OFF + srow + 16), "r"(ul[4]), "r"(ul[5]), "r"(ul[6]), "r"(ul[7]) : "memory");
    };

    auto cp_B = [&](int c, uint32_t stage) {
        CP16(stage + BH_OFF + srow,      gBh + (size_t)c * 64);
        CP16(stage + BH_OFF + srow + 16, gBh + (size_t)c * 64 + 16);
        CP16(stage + BL_OFF + srow,      gBl + (size_t)c * 64);
        CP16(stage + BL_OFF + srow + 16, gBl + (size_t)c * 64 + 16);
    };

    // ---- prologue: fill stage 0 ----
    {
        float4 av[4];
#pragma unroll
        for (int i = 0; i < 4; i++)
            av[i] = *reinterpret_cast<const float4*>(gA + i * 4);
        cp_B(0, sb);
        CP_COMMIT();
        store_A(av, sb);
        CP_WAIT0();
    }
    __syncthreads();

    for (int c = 0; c < NCHUNK; c++) {
        const uint32_t stage  = sb + (uint32_t)(c & 1) * STAGE_BYTES;
        const uint32_t nstage = sb + (uint32_t)((c + 1) & 1) * STAGE_BYTES;

        float4 av[4];
        if (c + 1 < NCHUNK) {
#pragma unroll
            for (int i = 0; i < 4; i++)
                av[i] = *reinterpret_cast<const float4*>(gA + (c + 1) * BKC + i * 4);
            cp_B(c + 1, nstage);
            CP_COMMIT();
        }

        // ---- compute current chunk: 2 k16-steps ----
#pragma unroll
        for (int ks = 0; ks < 2; ks++) {
            const uint32_t ko = ks * 32;
            uint32_t bh[2][4], bl[2][4];
#pragma unroll
            for (int ng = 0; ng < 2; ng++) {
                LDSM4(bh[ng], stage + BH_OFF + b_lm + ng * (16 * LDB) + ko);
                LDSM4(bl[ng], stage + BL_OFF + b_lm + ng * (16 * LDB) + ko);
            }
#pragma unroll
            for (int mt = 0; mt < 4; mt++) {
                uint32_t ah[4], al[4];
                LDSM4(ah, stage + AH_OFF + a_lm + mt * (16 * LDB) + ko);
                LDSM4(al, stage + AL_OFF + a_lm + mt * (16 * LDB) + ko);
#pragma unroll
                for (int nf = 0; nf < 4; nf++)
                    MMA_BF16(acc[mt][nf], ah,
                             bh[nf >> 1][(nf & 1) * 2], bh[nf >> 1][(nf & 1) * 2 + 1]);
#pragma unroll
                for (int nf = 0; nf < 4; nf++)
                    MMA_BF16(acc[mt][nf], ah,
                             bl[nf >> 1][(nf & 1) * 2], bl[nf >> 1][(nf & 1) * 2 + 1]);
#pragma unroll
                for (int nf = 0; nf < 4; nf++)
                    MMA_BF16(acc[mt][nf], al,
                             bh[nf >> 1][(nf & 1) * 2], bh[nf >> 1][(nf & 1) * 2 + 1]);
            }
        }

        if (c + 1 < NCHUNK) {
            store_A(av, nstage);
            CP_WAIT0();
        }
        __syncthreads();
    }

    // ---- row-norm exchange: combine halves, publish to smem ----
    sumsq += __shfl_xor_sync(0xffffffffu, sumsq, 1);
    float* rowsq = reinterpret_cast<float*>(smem);
    if (half == 0) rowsq[arow] = sumsq;
    __syncthreads();

    // ---- epilogue: scale by invh * invw, store ----
    float2 iw[4];
#pragma unroll
    for (int nf = 0; nf < 4; nf++) {
        const int col = nw * 32 + nf * 8 + (lane & 3) * 2;
        iw[nf] = *reinterpret_cast<const float2*>(g_inv_w2 + g * 128 + col);
    }
#pragma unroll
    for (int mt = 0; mt < 4; mt++) {
        const int rl = mw * 64 + mt * 16 + (lane >> 2);
        const float ih0 = 1.0f / fmaxf(sqrtf(rowsq[rl]), 1e-12f);
        const float ih1 = 1.0f / fmaxf(sqrtf(rowsq[rl + 8]), 1e-12f);
        const int row = m0 + rl;
#pragma unroll
        for (int nf = 0; nf < 4; nf++) {
            const int col = nw * 32 + nf * 8 + (lane & 3) * 2;
            if (col < K_) {
                float2 v0 = {acc[mt][nf][0] * ih0 * iw[nf].x,
                             acc[mt][nf][1] * ih0 * iw[nf].y};
                float2 v1 = {acc[mt][nf][2] * ih1 * iw[nf].x,
                             acc[mt][nf][3] * ih1 * iw[nf].y};
                *reinterpret_cast<float2*>(out + ((size_t)row * G_ + g) * K_ + col) = v0;
                *reinterpret_cast<float2*>(out + ((size_t)(row + 8) * G_ + g) * K_ + col) = v1;
            }
        }
    }
}

// ---------------------------------------------------------------------------
extern "C" void kernel_launch(void* const* d_in, const int* in_sizes, int n_in,
                              void* d_out, int out_size) {
    const float* h = (const float*)d_in[0];   // [512,100,768]
    const float* w = (const float*)d_in[1];   // [100,768,100]
    float* out = (float*)d_out;               // [512,100,100]
    (void)in_sizes; (void)n_in; (void)out_size;

    const int smem_bytes = 2 * STAGE_BYTES;   // 81920 per CTA -> 2 CTAs/SM
    cudaFuncSetAttribute(gemm_hmma_kernel,
                         cudaFuncAttributeMaxDynamicSharedMemorySize, smem_bytes);

    prep_w_kernel<<<dim3(16, G_), 256>>>(w);      // norm partials + split fused
    combine_w_kernel<<<G_, 128>>>();              // tiny invw table
    dim3 grid(B_ / 128, G_);
    gemm_hmma_kernel<<<grid, 256, smem_bytes>>>(h, out);
}

// round 14
// speedup vs baseline: 1.6286x; 1.1555x over previous
#include <cuda_runtime.h>
#include <cuda_bf16.h>
#include <cstdint>

// out[b,g,k] = sum_d (h[b,g,d]/||h||) * (w[g,d,k]/||w_col||)
// B=512, G=100, D=768, K=100.
// bf16 two-term split, 3-product HMMA, fp32 acc, double-buffered smem.
// Both norms commuted into the GEMM epilogue.
// W scratch kept in native [g][d][k] orientation (no transpose anywhere):
//   prep = pure streaming convert; GEMM B path uses ldmatrix.x4.trans.

#define B_ 512
#define G_ 100
#define D_ 768
#define K_ 100
#define KP 128
#define BKC 32              // k-chunk (d dimension)
#define NCHUNK (D_ / BKC)   // 24
#define LDB 80              // A smem row stride bytes (32 bf16 + pad)
#define LDBB 272            // B smem row stride bytes (128 bf16 + 16B pad)

#define AH_OFF 0            // 128 rows * 80  = 10240
#define AL_OFF 10240
#define BH_OFF 20480        // 32 rows * 272  = 8704
#define BL_OFF 29184
#define STAGE_BYTES 37888

// ---------------- device scratch ----------------
__device__ float g_wpart[4 * G_ * 128];     // norm_w partials [seg][g][k]
__device__ float g_inv_w2[G_ * 128];        // invw table [g][k] (0 for k>=100)
__device__ __nv_bfloat16 g_wt_hi[(size_t)G_ * D_ * KP];   // [g][d][k], .bss zeros
__device__ __nv_bfloat16 g_wt_lo[(size_t)G_ * D_ * KP];

// ---------------- helpers ----------------
__device__ __forceinline__ uint32_t smem_u32(const void* p) {
    uint32_t a;
    asm("{ .reg .u64 t; cvta.to.shared.u64 t, %1; cvt.u32.u64 %0, t; }"
        : "=r"(a) : "l"(p));
    return a;
}

#define MMA_BF16(d, a, b0, b1)                                              \
    asm volatile(                                                           \
        "mma.sync.aligned.m16n8k16.row.col.f32.bf16.bf16.f32 "              \
        "{%0,%1,%2,%3}, {%4,%5,%6,%7}, {%8,%9}, {%0,%1,%2,%3};"             \
        : "+f"(d[0]), "+f"(d[1]), "+f"(d[2]), "+f"(d[3])                    \
        : "r"(a[0]), "r"(a[1]), "r"(a[2]), "r"(a[3]), "r"(b0), "r"(b1))

#define LDSM4(r, addr)                                                      \
    asm volatile("ldmatrix.sync.aligned.m8n8.x4.shared.b16 "                \
                 "{%0,%1,%2,%3}, [%4];"                                     \
                 : "=r"((r)[0]), "=r"((r)[1]), "=r"((r)[2]), "=r"((r)[3])   \
                 : "r"(addr))

#define LDSM4T(r, addr)                                                     \
    asm volatile("ldmatrix.sync.aligned.m8n8.x4.trans.shared.b16 "          \
                 "{%0,%1,%2,%3}, [%4];"                                     \
                 : "=r"((r)[0]), "=r"((r)[1]), "=r"((r)[2]), "=r"((r)[3])   \
                 : "r"(addr))

#define CP16(dst, src)                                                      \
    asm volatile("cp.async.cg.shared.global [%0], [%1], 16;"                \
                 :: "r"(dst), "l"(src) : "memory")
#define CP_COMMIT() asm volatile("cp.async.commit_group;" ::: "memory")
#define CP_WAIT0()  asm volatile("cp.async.wait_group 0;" ::: "memory")

// ---------------------------------------------------------------------------
// prep_w: flat grid. Blocks 0..399: norm partials (seg = b%4, g = b/4).
// Blocks 400..7899: streaming convert w -> unnormalized bf16 hi/lo, native
// [g][d][k] layout (k>=100 stays zero from .bss). No smem, no transpose.
// ---------------------------------------------------------------------------
__global__ void prep_w_kernel(const float* __restrict__ w) {
    __shared__ float part[2][128];
    const int bz  = blockIdx.x;
    const int tid = threadIdx.x;

    if (bz < 400) {
        const int seg = bz & 3;
        const int g   = bz >> 2;
        const int k   = tid & 127;
        const int c   = tid >> 7;            // 0..1, 96 d each
        float s = 0.f;
        if (k < K_) {
            const float* base = w + (size_t)g * D_ * K_
                                  + ((size_t)seg * 192 + (size_t)c * 96) * K_ + k;
#pragma unroll 8
            for (int d = 0; d < 96; d++) {
                float v = base[(size_t)d * K_];
                s += v * v;
            }
        }
        part[c][k] = s;
        __syncthreads();
        if (c == 0)
            g_wpart[((size_t)seg * G_ + g) * 128 + k] = part[0][k] + part[1][k];
        return;
    }

    // ---- streaming convert: 4 k-elems per thread ----
    const int t   = (bz - 400) * 256 + tid;    // 0 .. 1,919,999
    const int row = t / 25;                    // g*D + d  (0 .. 76799)
    const int j   = t % 25;                    // k quad: k = 4j .. 4j+3
    float4 v = *reinterpret_cast<const float4*>(w + (size_t)row * K_ + 4 * j);

    __nv_bfloat162 h0 = __float22bfloat162_rn(make_float2(v.x, v.y));
    __nv_bfloat162 h1 = __float22bfloat162_rn(make_float2(v.z, v.w));
    float2 f0 = __bfloat1622float2(h0), f1 = __bfloat1622float2(h1);
    __nv_bfloat162 l0 = __float22bfloat162_rn(make_float2(v.x - f0.x, v.y - f0.y));
    __nv_bfloat162 l1 = __float22bfloat162_rn(make_float2(v.z - f1.x, v.w - f1.y));

    uint2 uh, ul;
    uh.x = *reinterpret_cast<uint32_t*>(&h0);
    uh.y = *reinterpret_cast<uint32_t*>(&h1);
    ul.x = *reinterpret_cast<uint32_t*>(&l0);
    ul.y = *reinterpret_cast<uint32_t*>(&l1);
    *reinterpret_cast<uint2*>(g_wt_hi + (size_t)row * KP + 4 * j) = uh;
    *reinterpret_cast<uint2*>(g_wt_lo + (size_t)row * KP + 4 * j) = ul;
}

// ---------------------------------------------------------------------------
// combine: invw table from partials. 100 blocks x 128 threads.
// ---------------------------------------------------------------------------
__global__ void combine_w_kernel() {
    const int g = blockIdx.x;
    const int k = threadIdx.x;
    float s = g_wpart[((size_t)0 * G_ + g) * 128 + k]
            + g_wpart[((size_t)1 * G_ + g) * 128 + k]
            + g_wpart[((size_t)2 * G_ + g) * 128 + k]
            + g_wpart[((size_t)3 * G_ + g) * 128 + k];
    g_inv_w2[g * 128 + k] = (k < K_) ? 1.0f / fmaxf(sqrtf(s), 1e-12f) : 0.f;
}

// ---------------------------------------------------------------------------
// HMMA GEMM. CTA = (g, 128 rows), 8 warps: mw = warp&1 (64 rows),
// nw = warp>>1 (32 cols). Warp tile 64x32, 3 bf16 products, fp32 acc.
// A raw-split with sumsq; B tiles k-major [32d][128k] via ldmatrix.trans;
// invh and invw applied in epilogue.
// ---------------------------------------------------------------------------
__global__ __launch_bounds__(256, 2)
void gemm_hmma_kernel(const float* __restrict__ h, float* __restrict__ out) {
    extern __shared__ char smem[];
    const uint32_t sb = smem_u32(smem);
    const int tid  = threadIdx.x;
    const int lane = tid & 31;
    const int warp = tid >> 5;
    const int mw = warp & 1;
    const int nw = warp >> 1;
    const int g  = blockIdx.y;
    const int m0 = blockIdx.x * 128;

    // ---- A global mapping: 2 threads per row, 16 elems each ----
    const int arow = tid >> 1;
    const int half = tid & 1;
    const float* gA = h + ((size_t)(m0 + arow) * G_ + g) * D_ + half * 16;
    const uint32_t srow = arow * LDB + half * 32;

    // ---- B global mapping: chunk is 8KB contiguous [32 d][128 k] ----
    const char* gB_h = reinterpret_cast<const char*>(g_wt_hi + (size_t)g * D_ * KP);
    const char* gB_l = reinterpret_cast<const char*>(g_wt_lo + (size_t)g * D_ * KP);
    const int bid0 = tid, bid1 = tid + 256;
    const uint32_t bsrc0 = (bid0 >> 4) * 256 + (bid0 & 15) * 16;
    const uint32_t bdst0 = (bid0 >> 4) * LDBB + (bid0 & 15) * 16;
    const uint32_t bsrc1 = (bid1 >> 4) * 256 + (bid1 & 15) * 16;
    const uint32_t bdst1 = (bid1 >> 4) * LDBB + (bid1 & 15) * 16;

    // ldmatrix base addresses (stage-relative)
    const uint32_t a_lm = (mw * 64 + (lane & 15)) * LDB + (lane >> 4) * 16;
    // B trans: krow = ((lane>>3)&1)*8 + (lane&7); n byte = (lane>>4)*16 + nw*64
    const uint32_t b_lm = (((lane >> 3) & 1) * 8 + (lane & 7)) * LDBB
                        + (lane >> 4) * 16 + nw * 64;

    float acc[4][4][4];   // [mt][nf][reg]
#pragma unroll
    for (int mt = 0; mt < 4; mt++)
#pragma unroll
        for (int nf = 0; nf < 4; nf++)
#pragma unroll
            for (int r = 0; r < 4; r++) acc[mt][nf][r] = 0.f;

    float sumsq = 0.f;

    // ---- A convert+store: 16 fp32 -> hi/lo bf16, accumulate sumsq ----
    auto store_A = [&](const float4* av, uint32_t stage) {
        uint32_t uh[8], ul[8];
#pragma unroll
        for (int i = 0; i < 4; i++) {
            float x0 = av[i].x, x1 = av[i].y, x2 = av[i].z, x3 = av[i].w;
            sumsq = fmaf(x0, x0, sumsq);
            sumsq = fmaf(x1, x1, sumsq);
            sumsq = fmaf(x2, x2, sumsq);
            sumsq = fmaf(x3, x3, sumsq);
            __nv_bfloat162 h0 = __float22bfloat162_rn(make_float2(x0, x1));
            __nv_bfloat162 h1 = __float22bfloat162_rn(make_float2(x2, x3));
            float2 f0 = __bfloat1622float2(h0), f1 = __bfloat1622float2(h1);
            __nv_bfloat162 l0 = __float22bfloat162_rn(make_float2(x0 - f0.x, x1 - f0.y));
            __nv_bfloat162 l1 = __float22bfloat162_rn(make_float2(x2 - f1.x, x3 - f1.y));
            uh[i * 2]     = *reinterpret_cast<uint32_t*>(&h0);
            uh[i * 2 + 1] = *reinterpret_cast<uint32_t*>(&h1);
            ul[i * 2]     = *reinterpret_cast<uint32_t*>(&l0);
            ul[i * 2 + 1] = *reinterpret_cast<uint32_t*>(&l1);
        }
        asm volatile("st.shared.v4.b32 [%0], {%1,%2,%3,%4};"
            :: "r"(stage + AH_OFF + srow), "r"(uh[0]), "r"(uh[1]), "r"(uh[2]), "r"(uh[3]) : "memory");
        asm volatile("st.shared.v4.b32 [%0], {%1,%2,%3,%4};"
            :: "r"(stage + AH_OFF + srow + 16), "r"(uh[4]), "r"(uh[5]), "r"(uh[6]), "r"(uh[7]) : "memory");
        asm volatile("st.shared.v4.b32 [%0], {%1,%2,%3,%4};"
            :: "r"(stage + AL_OFF + srow), "r"(ul[0]), "r"(ul[1]), "r"(ul[2]), "r"(ul[3]) : "memory");
        asm volatile("st.shared.v4.b32 [%0], {%1,%2,%3,%4};"
            :: "r"(stage + AL_OFF + srow + 16), "r"(ul[4]), "r"(ul[5]), "r"(ul[6]), "r"(ul[7]) : "memory");
    };

    auto cp_B = [&](int c, uint32_t stage) {
        const char* sh = gB_h + (size_t)c * 8192;
        const char* sl = gB_l + (size_t)c * 8192;
        CP16(stage + BH_OFF + bdst0, sh + bsrc0);
        CP16(stage + BH_OFF + bdst1, sh + bsrc1);
        CP16(stage + BL_OFF + bdst0, sl + bsrc0);
        CP16(stage + BL_OFF + bdst1, sl + bsrc1);
    };

    // ---- prologue: fill stage 0 ----
    {
        float4 av[4];
#pragma unroll
        for (int i = 0; i < 4; i++)
            av[i] = *reinterpret_cast<const float4*>(gA + i * 4);
        cp_B(0, sb);
        CP_COMMIT();
        store_A(av, sb);
        CP_WAIT0();
    }
    __syncthreads();

    for (int c = 0; c < NCHUNK; c++) {
        const uint32_t stage  = sb + (uint32_t)(c & 1) * STAGE_BYTES;
        const uint32_t nstage = sb + (uint32_t)((c + 1) & 1) * STAGE_BYTES;

        float4 av[4];
        if (c + 1 < NCHUNK) {
#pragma unroll
            for (int i = 0; i < 4; i++)
                av[i] = *reinterpret_cast<const float4*>(gA + (c + 1) * BKC + i * 4);
            cp_B(c + 1, nstage);
            CP_COMMIT();
        }

        // ---- compute current chunk: 2 k16-steps ----
#pragma unroll
        for (int ks = 0; ks < 2; ks++) {
            const uint32_t koA = ks * 32;           // A: 16 bf16 = 32 bytes
            const uint32_t koB = ks * 16 * LDBB;    // B: 16 k-rows
            uint32_t bh[2][4], bl[2][4];
#pragma unroll
            for (int nhalf = 0; nhalf < 2; nhalf++) {
                LDSM4T(bh[nhalf], stage + BH_OFF + koB + b_lm + nhalf * 32);
                LDSM4T(bl[nhalf], stage + BL_OFF + koB + b_lm + nhalf * 32);
            }
#pragma unroll
            for (int mt = 0; mt < 4; mt++) {
                uint32_t ah[4], al[4];
                LDSM4(ah, stage + AH_OFF + a_lm + mt * (16 * LDB) + koA);
                LDSM4(al, stage + AL_OFF + a_lm + mt * (16 * LDB) + koA);
#pragma unroll
                for (int nf = 0; nf < 4; nf++)
                    MMA_BF16(acc[mt][nf], ah,
                             bh[nf >> 1][(nf & 1) * 2], bh[nf >> 1][(nf & 1) * 2 + 1]);
#pragma unroll
                for (int nf = 0; nf < 4; nf++)
                    MMA_BF16(acc[mt][nf], ah,
                             bl[nf >> 1][(nf & 1) * 2], bl[nf >> 1][(nf & 1) * 2 + 1]);
#pragma unroll
                for (int nf = 0; nf < 4; nf++)
                    MMA_BF16(acc[mt][nf], al,
                             bh[nf >> 1][(nf & 1) * 2], bh[nf >> 1][(nf & 1) * 2 + 1]);
            }
        }

        if (c + 1 < NCHUNK) {
            store_A(av, nstage);
            CP_WAIT0();
        }
        __syncthreads();
    }

    // ---- row-norm exchange ----
    sumsq += __shfl_xor_sync(0xffffffffu, sumsq, 1);
    float* rowsq = reinterpret_cast<float*>(smem);
    if (half == 0) rowsq[arow] = sumsq;
    __syncthreads();

    // ---- epilogue: scale by invh * invw, store ----
    float2 iw[4];
#pragma unroll
    for (int nf = 0; nf < 4; nf++) {
        const int col = nw * 32 + nf * 8 + (lane & 3) * 2;
        iw[nf] = *reinterpret_cast<const float2*>(g_inv_w2 + g * 128 + col);
    }
#pragma unroll
    for (int mt = 0; mt < 4; mt++) {
        const int rl = mw * 64 + mt * 16 + (lane >> 2);
        const float ih0 = 1.0f / fmaxf(sqrtf(rowsq[rl]), 1e-12f);
        const float ih1 = 1.0f / fmaxf(sqrtf(rowsq[rl + 8]), 1e-12f);
        const int row = m0 + rl;
#pragma unroll
        for (int nf = 0; nf < 4; nf++) {
            const int col = nw * 32 + nf * 8 + (lane & 3) * 2;
            if (col < K_) {
                float2 v0 = {acc[mt][nf][0] * ih0 * iw[nf].x,
                             acc[mt][nf][1] * ih0 * iw[nf].y};
                float2 v1 = {acc[mt][nf][2] * ih1 * iw[nf].x,
                             acc[mt][nf][3] * ih1 * iw[nf].y};
                *reinterpret_cast<float2*>(out + ((size_t)row * G_ + g) * K_ + col) = v0;
                *reinterpret_cast<float2*>(out + ((size_t)(row + 8) * G_ + g) * K_ + col) = v1;
            }
        }
    }
}

// ---------------------------------------------------------------------------
extern "C" void kernel_launch(void* const* d_in, const int* in_sizes, int n_in,
                              void* d_out, int out_size) {
    const float* h = (const float*)d_in[0];   // [512,100,768]
    const float* w = (const float*)d_in[1];   // [100,768,100]
    float* out = (float*)d_out;               // [512,100,100]
    (void)in_sizes; (void)n_in; (void)out_size;

    const int smem_bytes = 2 * STAGE_BYTES;   // 75776 per CTA -> 2 CTAs/SM
    cudaFuncSetAttribute(gemm_hmma_kernel,
                         cudaFuncAttributeMaxDynamicSharedMemorySize, smem_bytes);

    prep_w_kernel<<<400 + 7500, 256>>>(w);    // norm partials + streaming split
    combine_w_kernel<<<G_, 128>>>();          // tiny invw table
    dim3 grid(B_ / 128, G_);
    gemm_hmma_kernel<<<grid, 256, smem_bytes>>>(h, out);
}